// round 15
// baseline (speedup 1.0000x reference)
#include <cuda_runtime.h>
#include <cstdint>

// LinearAttention per (b,l) site (16384 sites):
//   qf=elu(q)+1, kf=elu(k)+1 [32,64]; A = qf@kf^T [32,32];
//   y[h] = L^-0.5/(rowsum(A)+eps); x = diag(y) A V [32,64].
// R15 = R14 (tf32 mma.sync + ldmatrix stage-1, in-register A' permute,
//   raw-f32-as-tf32 V, per-group cp.async staging with per-thread elu)
//   + L2::256B prefetch hints on the dense cp.async read streams
//   + evict-first (.cs) output stores to keep the write stream out of L2.

#define RP  68      // sQ/sK pitch in words (272B): ldmatrix phases conflict-free
#define VPW 72      // sV pitch in words (288B): stage-2 lane addr ≡ 8t+g -> CF
#define EPSV 1e-6f
#define RSQRT_L 0.022097086912079608f   // 2048^-0.5

typedef uint32_t u32;

__device__ __forceinline__ u32 elu1_tf_bits(u32 xb) {
    float x = __uint_as_float(xb);
    float e;
    asm("ex2.approx.ftz.f32 %0, %1;" : "=f"(e) : "f"(x * 1.4426950408889634f));
    float r = x > 0.0f ? x + 1.0f : e;
    u32 o;
    asm("cvt.rna.tf32.f32 %0, %1;" : "=r"(o) : "f"(r));
    return o;
}
__device__ __forceinline__ u32 f2tf(float x) {
    u32 o;
    asm("cvt.rna.tf32.f32 %0, %1;" : "=r"(o) : "f"(x));
    return o;
}
// D(16x8,f32) += A(16x8,tf32,row) * B(8x8,tf32,col)
__device__ __forceinline__ void mma8(float* d, const u32* a, u32 b0, u32 b1) {
    asm("mma.sync.aligned.m16n8k8.row.col.f32.tf32.tf32.f32 "
        "{%0,%1,%2,%3}, {%4,%5,%6,%7}, {%8,%9}, {%0,%1,%2,%3};"
        : "+f"(d[0]), "+f"(d[1]), "+f"(d[2]), "+f"(d[3])
        : "r"(a[0]), "r"(a[1]), "r"(a[2]), "r"(a[3]), "r"(b0), "r"(b1));
}
__device__ __forceinline__ void ldsm4(u32* r, u32 addr) {
    asm volatile("ldmatrix.sync.aligned.m8n8.x4.shared.b16 {%0,%1,%2,%3}, [%4];"
        : "=r"(r[0]), "=r"(r[1]), "=r"(r[2]), "=r"(r[3]) : "r"(addr));
}
__device__ __forceinline__ u32 smem_u32(const void* p) {
    u32 a;
    asm("{ .reg .u64 t; cvta.to.shared.u64 t, %1; cvt.u32.u64 %0, t; }"
        : "=r"(a) : "l"(p));
    return a;
}
__device__ __forceinline__ void cpa16(u32 dst, const void* src) {
    asm volatile("cp.async.cg.shared.global.L2::256B [%0], [%1], 16;"
                 :: "r"(dst), "l"(src) : "memory");
}
__device__ __forceinline__ void stg_cs2(float* p, float a, float b) {
    asm volatile("st.global.cs.v2.f32 [%0], {%1, %2};"
                 :: "l"(p), "f"(a), "f"(b) : "memory");
}

__global__ void __launch_bounds__(64, 6) linattn_kernel(
    const float* __restrict__ Q, const float* __restrict__ K,
    const float* __restrict__ V, float* __restrict__ O)
{
    __shared__ __align__(16) u32 sQ[32 * RP];    // 8704 B  raw f32 -> tf32(elu+1)
    __shared__ __align__(16) u32 sK[32 * RP];    // 8704 B  raw f32 -> tf32(elu+1)
    __shared__ __align__(16) u32 sV[32 * VPW];   // 9216 B  raw f32 (used as tf32)

    const int tid = threadIdx.x;
    const int w   = tid >> 5;        // warp 0/1: owns output rows 16w..16w+15
    const int ln  = tid & 31;
    const int g   = ln >> 2;         // groupID 0..7
    const int t   = ln & 3;          // threadID-in-group 0..3
    const size_t site = blockIdx.x;

    const float4* q4 = (const float4*)(Q + site * 2048);
    const float4* k4 = (const float4*)(K + site * 2048);
    const float4* v4 = (const float4*)(V + site * 2048);

    // ---- Stage ALL inputs via cp.async. Groups: Q(0), K(1), V(2). ----
    const u32 sqb = smem_u32(sQ), skb = smem_u32(sK), svb = smem_u32(sV);
    #pragma unroll
    for (int it = 0; it < 8; ++it) {
        int f  = tid + it * 64;
        int h  = f >> 4;
        int e4 = (f & 15) << 2;
        cpa16(sqb + ((h * RP + e4) << 2), q4 + f);
    }
    asm volatile("cp.async.commit_group;" ::: "memory");   // group 0: Q
    #pragma unroll
    for (int it = 0; it < 8; ++it) {
        int f  = tid + it * 64;
        int h  = f >> 4;
        int e4 = (f & 15) << 2;
        cpa16(skb + ((h * RP + e4) << 2), k4 + f);
    }
    asm volatile("cp.async.commit_group;" ::: "memory");   // group 1: K
    #pragma unroll
    for (int it = 0; it < 8; ++it) {
        int f  = tid + it * 64;
        int h  = f >> 4;
        int e4 = (f & 15) << 2;
        cpa16(svb + ((h * VPW + e4) << 2), v4 + f);
    }
    asm volatile("cp.async.commit_group;" ::: "memory");   // group 2: V

    // ---- Per-thread: transform own Q words as soon as they land ----
    asm volatile("cp.async.wait_group 2;" ::: "memory");   // Q arrived
    #pragma unroll
    for (int it = 0; it < 8; ++it) {
        int f  = tid + it * 64;
        int h  = f >> 4;
        int e4 = (f & 15) << 2;
        uint4* pq = (uint4*)&sQ[h * RP + e4];
        uint4 a = *pq;
        a.x = elu1_tf_bits(a.x); a.y = elu1_tf_bits(a.y);
        a.z = elu1_tf_bits(a.z); a.w = elu1_tf_bits(a.w);
        *pq = a;
    }
    asm volatile("cp.async.wait_group 1;" ::: "memory");   // K arrived
    #pragma unroll
    for (int it = 0; it < 8; ++it) {
        int f  = tid + it * 64;
        int h  = f >> 4;
        int e4 = (f & 15) << 2;
        uint4* pk = (uint4*)&sK[h * RP + e4];
        uint4 b = *pk;
        b.x = elu1_tf_bits(b.x); b.y = elu1_tf_bits(b.y);
        b.z = elu1_tf_bits(b.z); b.w = elu1_tf_bits(b.w);
        *pk = b;
    }
    __syncthreads();                     // barB: transformed Q/K visible to all

    // ===== Stage 1: D[16,32] = Qf[rows 16w..] @ Kf^T   (k=64: 8 k-tiles) ====
    float D[4][4];
    #pragma unroll
    for (int nt = 0; nt < 4; ++nt)
        #pragma unroll
        for (int r = 0; r < 4; ++r) D[nt][r] = 0.0f;

    {
        const u32 qa = sqb
            + (((16 * w + (ln & 15)) * RP + ((ln & 16) ? 4 : 0)) << 2);
        const u32 kb = skb
            + (((((ln & 16) ? 8 : 0) + (ln & 7)) * RP + ((ln & 8) ? 4 : 0)) << 2);

        #pragma unroll
        for (int kt = 0; kt < 8; ++kt) {
            u32 a[4], b01[4], b23[4];
            ldsm4(a,   qa + kt * 32);
            ldsm4(b01, kb + kt * 32);                  // nt 0,1
            ldsm4(b23, kb + 16 * RP * 4 + kt * 32);    // nt 2,3
            mma8(D[0], a, b01[0], b01[1]);
            mma8(D[1], a, b01[2], b01[3]);
            mma8(D[2], a, b23[0], b23[1]);
            mma8(D[3], a, b23[2], b23[3]);
        }
    }

    // ---- y from rowsums (rows 16w+g, 16w+8+g), fold into A' ----
    float s0 = 0.0f, s1 = 0.0f;
    #pragma unroll
    for (int nt = 0; nt < 4; ++nt) {
        s0 += D[nt][0] + D[nt][1];
        s1 += D[nt][2] + D[nt][3];
    }
    s0 += __shfl_xor_sync(0xffffffffu, s0, 1);
    s0 += __shfl_xor_sync(0xffffffffu, s0, 2);
    s1 += __shfl_xor_sync(0xffffffffu, s1, 1);
    s1 += __shfl_xor_sync(0xffffffffu, s1, 2);
    const float y0 = RSQRT_L / (s0 + EPSV);
    const float y1 = RSQRT_L / (s1 + EPSV);

    // ---- Register permute: D frags (cols 2t,2t+1) -> A frags (cols t,t+4) --
    u32 aA[4][4];
    const int src0 = (ln & ~3) | (t >> 1);
    const int src2 = src0 + 2;
    #pragma unroll
    for (int nt = 0; nt < 4; ++nt) {
        u32 c0 = f2tf(D[nt][0] * y0), c1 = f2tf(D[nt][1] * y0);
        u32 c2 = f2tf(D[nt][2] * y1), c3 = f2tf(D[nt][3] * y1);
        u32 u0 = __shfl_sync(0xffffffffu, c0, src0);
        u32 u1 = __shfl_sync(0xffffffffu, c1, src0);
        u32 p0 = __shfl_sync(0xffffffffu, c0, src2);
        u32 p1 = __shfl_sync(0xffffffffu, c1, src2);
        aA[nt][0] = (t & 1) ? u1 : u0;
        aA[nt][2] = (t & 1) ? p1 : p0;
        u0 = __shfl_sync(0xffffffffu, c2, src0);
        u1 = __shfl_sync(0xffffffffu, c3, src0);
        p0 = __shfl_sync(0xffffffffu, c2, src2);
        p1 = __shfl_sync(0xffffffffu, c3, src2);
        aA[nt][1] = (t & 1) ? u1 : u0;
        aA[nt][3] = (t & 1) ? p1 : p0;
    }

    // ---- V landed? (its copy had staging + stage 1 to complete) ----
    asm volatile("cp.async.wait_group 0;" ::: "memory");
    __syncthreads();                     // barC: all threads' V copies visible

    // ===== Stage 2: X[16,64] = A'[16,32] @ V[32,64]   (k=32: 4 k-tiles) =====
    float X[8][4];
    #pragma unroll
    for (int nt = 0; nt < 8; ++nt)
        #pragma unroll
        for (int r = 0; r < 4; ++r) X[nt][r] = 0.0f;

    #pragma unroll
    for (int kt = 0; kt < 4; ++kt) {
        const u32* vb = sV + (kt * 8 + t) * VPW + g;
        #pragma unroll
        for (int nt = 0; nt < 8; ++nt) {
            mma8(X[nt], aA[kt], vb[nt * 8], vb[nt * 8 + 4 * VPW]);
        }
    }

    // ---- Epilogue: evict-first STG.64, rows 16w+g and 16w+8+g ----
    float* ob = O + site * 2048 + (16 * w + g) * 64 + 2 * t;
    #pragma unroll
    for (int nt = 0; nt < 8; ++nt) {
        stg_cs2(ob + nt * 8,          X[nt][0], X[nt][1]);
        stg_cs2(ob + 8 * 64 + nt * 8, X[nt][2], X[nt][3]);
    }
}

extern "C" void kernel_launch(void* const* d_in, const int* in_sizes, int n_in,
                              void* d_out, int out_size) {
    const float* Q = (const float*)d_in[0];
    const float* K = (const float*)d_in[1];
    const float* V = (const float*)d_in[2];
    float* O = (float*)d_out;
    int nsites = in_sizes[0] / 2048;   // B*L = 16384
    linattn_kernel<<<nsites, 64>>>(Q, K, V, O);
}

// round 16
// speedup vs baseline: 1.0070x; 1.0070x over previous
#include <cuda_runtime.h>
#include <cstdint>

// LinearAttention per (b,l) site (16384 sites):
//   qf=elu(q)+1, kf=elu(k)+1 [32,64]; A = qf@kf^T [32,32];
//   y[h] = L^-0.5/(rowsum(A)+eps); x = diag(y) A V [32,64].
// FINAL (== R14, best measured 82.5us):
//   - 2x-FLOP re-association: A = qf kf^T then A V (vs Q (K^T V))
//   - both GEMMs on tensor cores: mma.sync.m16n8k8 tf32 (rna-converted Q/K;
//     V consumed as raw f32 bits, bit-compatible with tf32)
//   - warp w owns output rows 16w..16w+15 end-to-end; stage-1 D frags are
//     y-scaled and register-permuted (shfl) into stage-2 A frags -> A' never
//     touches smem; single data barrier after staging
//   - stage-1 fragments via ldmatrix.m8n8.x4 (conflict-free pitch 68)
//   - all staging via cp.async in 3 commit groups (Q/K/V); per-thread waits
//     + in-place smem elu (each thread transforms exactly its own copies);
//     V wait deferred past stage 1 so its DRAM fetch hides under compute
//   - 64-thread CTAs, 8/SM: maximal per-SM load-issuer count (DRAM-bound)

#define RP  68      // sQ/sK pitch in words (272B): ldmatrix phases conflict-free
#define VPW 72      // sV pitch in words (288B): stage-2 lane addr ≡ 8t+g -> CF
#define EPSV 1e-6f
#define RSQRT_L 0.022097086912079608f   // 2048^-0.5

typedef uint32_t u32;

__device__ __forceinline__ u32 elu1_tf_bits(u32 xb) {
    float x = __uint_as_float(xb);
    float e;
    asm("ex2.approx.ftz.f32 %0, %1;" : "=f"(e) : "f"(x * 1.4426950408889634f));
    float r = x > 0.0f ? x + 1.0f : e;
    u32 o;
    asm("cvt.rna.tf32.f32 %0, %1;" : "=r"(o) : "f"(r));
    return o;
}
__device__ __forceinline__ u32 f2tf(float x) {
    u32 o;
    asm("cvt.rna.tf32.f32 %0, %1;" : "=r"(o) : "f"(x));
    return o;
}
// D(16x8,f32) += A(16x8,tf32,row) * B(8x8,tf32,col)
__device__ __forceinline__ void mma8(float* d, const u32* a, u32 b0, u32 b1) {
    asm("mma.sync.aligned.m16n8k8.row.col.f32.tf32.tf32.f32 "
        "{%0,%1,%2,%3}, {%4,%5,%6,%7}, {%8,%9}, {%0,%1,%2,%3};"
        : "+f"(d[0]), "+f"(d[1]), "+f"(d[2]), "+f"(d[3])
        : "r"(a[0]), "r"(a[1]), "r"(a[2]), "r"(a[3]), "r"(b0), "r"(b1));
}
__device__ __forceinline__ void ldsm4(u32* r, u32 addr) {
    asm volatile("ldmatrix.sync.aligned.m8n8.x4.shared.b16 {%0,%1,%2,%3}, [%4];"
        : "=r"(r[0]), "=r"(r[1]), "=r"(r[2]), "=r"(r[3]) : "r"(addr));
}
__device__ __forceinline__ u32 smem_u32(const void* p) {
    u32 a;
    asm("{ .reg .u64 t; cvta.to.shared.u64 t, %1; cvt.u32.u64 %0, t; }"
        : "=r"(a) : "l"(p));
    return a;
}
__device__ __forceinline__ void cpa16(u32 dst, const void* src) {
    asm volatile("cp.async.cg.shared.global [%0], [%1], 16;"
                 :: "r"(dst), "l"(src) : "memory");
}

__global__ void __launch_bounds__(64, 6) linattn_kernel(
    const float* __restrict__ Q, const float* __restrict__ K,
    const float* __restrict__ V, float* __restrict__ O)
{
    __shared__ __align__(16) u32 sQ[32 * RP];    // 8704 B  raw f32 -> tf32(elu+1)
    __shared__ __align__(16) u32 sK[32 * RP];    // 8704 B  raw f32 -> tf32(elu+1)
    __shared__ __align__(16) u32 sV[32 * VPW];   // 9216 B  raw f32 (used as tf32)

    const int tid = threadIdx.x;
    const int w   = tid >> 5;        // warp 0/1: owns output rows 16w..16w+15
    const int ln  = tid & 31;
    const int g   = ln >> 2;         // groupID 0..7
    const int t   = ln & 3;          // threadID-in-group 0..3
    const size_t site = blockIdx.x;

    const float4* q4 = (const float4*)(Q + site * 2048);
    const float4* k4 = (const float4*)(K + site * 2048);
    const float4* v4 = (const float4*)(V + site * 2048);

    // ---- Stage ALL inputs via cp.async. Groups: Q(0), K(1), V(2). ----
    const u32 sqb = smem_u32(sQ), skb = smem_u32(sK), svb = smem_u32(sV);
    #pragma unroll
    for (int it = 0; it < 8; ++it) {
        int f  = tid + it * 64;
        int h  = f >> 4;
        int e4 = (f & 15) << 2;
        cpa16(sqb + ((h * RP + e4) << 2), q4 + f);
    }
    asm volatile("cp.async.commit_group;" ::: "memory");   // group 0: Q
    #pragma unroll
    for (int it = 0; it < 8; ++it) {
        int f  = tid + it * 64;
        int h  = f >> 4;
        int e4 = (f & 15) << 2;
        cpa16(skb + ((h * RP + e4) << 2), k4 + f);
    }
    asm volatile("cp.async.commit_group;" ::: "memory");   // group 1: K
    #pragma unroll
    for (int it = 0; it < 8; ++it) {
        int f  = tid + it * 64;
        int h  = f >> 4;
        int e4 = (f & 15) << 2;
        cpa16(svb + ((h * VPW + e4) << 2), v4 + f);
    }
    asm volatile("cp.async.commit_group;" ::: "memory");   // group 2: V

    // ---- Per-thread: transform own Q words as soon as they land ----
    // (wait_group is per-thread; each thread transforms exactly the words it
    //  copied, so no __syncthreads is needed before these passes)
    asm volatile("cp.async.wait_group 2;" ::: "memory");   // Q arrived
    #pragma unroll
    for (int it = 0; it < 8; ++it) {
        int f  = tid + it * 64;
        int h  = f >> 4;
        int e4 = (f & 15) << 2;
        uint4* pq = (uint4*)&sQ[h * RP + e4];
        uint4 a = *pq;
        a.x = elu1_tf_bits(a.x); a.y = elu1_tf_bits(a.y);
        a.z = elu1_tf_bits(a.z); a.w = elu1_tf_bits(a.w);
        *pq = a;
    }
    asm volatile("cp.async.wait_group 1;" ::: "memory");   // K arrived
    #pragma unroll
    for (int it = 0; it < 8; ++it) {
        int f  = tid + it * 64;
        int h  = f >> 4;
        int e4 = (f & 15) << 2;
        uint4* pk = (uint4*)&sK[h * RP + e4];
        uint4 b = *pk;
        b.x = elu1_tf_bits(b.x); b.y = elu1_tf_bits(b.y);
        b.z = elu1_tf_bits(b.z); b.w = elu1_tf_bits(b.w);
        *pk = b;
    }
    __syncthreads();                     // barB: transformed Q/K visible to all

    // ===== Stage 1: D[16,32] = Qf[rows 16w..] @ Kf^T   (k=64: 8 k-tiles) ====
    float D[4][4];
    #pragma unroll
    for (int nt = 0; nt < 4; ++nt)
        #pragma unroll
        for (int r = 0; r < 4; ++r) D[nt][r] = 0.0f;

    {
        const u32 qa = sqb
            + (((16 * w + (ln & 15)) * RP + ((ln & 16) ? 4 : 0)) << 2);
        const u32 kb = skb
            + (((((ln & 16) ? 8 : 0) + (ln & 7)) * RP + ((ln & 8) ? 4 : 0)) << 2);

        #pragma unroll
        for (int kt = 0; kt < 8; ++kt) {
            u32 a[4], b01[4], b23[4];
            ldsm4(a,   qa + kt * 32);
            ldsm4(b01, kb + kt * 32);                  // nt 0,1
            ldsm4(b23, kb + 16 * RP * 4 + kt * 32);    // nt 2,3
            mma8(D[0], a, b01[0], b01[1]);
            mma8(D[1], a, b01[2], b01[3]);
            mma8(D[2], a, b23[0], b23[1]);
            mma8(D[3], a, b23[2], b23[3]);
        }
    }

    // ---- y from rowsums (rows 16w+g, 16w+8+g), fold into A' ----
    float s0 = 0.0f, s1 = 0.0f;
    #pragma unroll
    for (int nt = 0; nt < 4; ++nt) {
        s0 += D[nt][0] + D[nt][1];
        s1 += D[nt][2] + D[nt][3];
    }
    s0 += __shfl_xor_sync(0xffffffffu, s0, 1);
    s0 += __shfl_xor_sync(0xffffffffu, s0, 2);
    s1 += __shfl_xor_sync(0xffffffffu, s1, 1);
    s1 += __shfl_xor_sync(0xffffffffu, s1, 2);
    const float y0 = RSQRT_L / (s0 + EPSV);
    const float y1 = RSQRT_L / (s1 + EPSV);

    // ---- Register permute: D frags (cols 2t,2t+1) -> A frags (cols t,t+4) --
    u32 aA[4][4];
    const int src0 = (ln & ~3) | (t >> 1);
    const int src2 = src0 + 2;
    #pragma unroll
    for (int nt = 0; nt < 4; ++nt) {
        u32 c0 = f2tf(D[nt][0] * y0), c1 = f2tf(D[nt][1] * y0);
        u32 c2 = f2tf(D[nt][2] * y1), c3 = f2tf(D[nt][3] * y1);
        u32 u0 = __shfl_sync(0xffffffffu, c0, src0);
        u32 u1 = __shfl_sync(0xffffffffu, c1, src0);
        u32 p0 = __shfl_sync(0xffffffffu, c0, src2);
        u32 p1 = __shfl_sync(0xffffffffu, c1, src2);
        aA[nt][0] = (t & 1) ? u1 : u0;
        aA[nt][2] = (t & 1) ? p1 : p0;
        u0 = __shfl_sync(0xffffffffu, c2, src0);
        u1 = __shfl_sync(0xffffffffu, c3, src0);
        p0 = __shfl_sync(0xffffffffu, c2, src2);
        p1 = __shfl_sync(0xffffffffu, c3, src2);
        aA[nt][1] = (t & 1) ? u1 : u0;
        aA[nt][3] = (t & 1) ? p1 : p0;
    }

    // ---- V landed? (its copy had staging + stage 1 to complete) ----
    asm volatile("cp.async.wait_group 0;" ::: "memory");
    __syncthreads();                     // barC: all threads' V copies visible

    // ===== Stage 2: X[16,64] = A'[16,32] @ V[32,64]   (k=32: 4 k-tiles) =====
    float X[8][4];
    #pragma unroll
    for (int nt = 0; nt < 8; ++nt)
        #pragma unroll
        for (int r = 0; r < 4; ++r) X[nt][r] = 0.0f;

    #pragma unroll
    for (int kt = 0; kt < 4; ++kt) {
        const u32* vb = sV + (kt * 8 + t) * VPW + g;
        #pragma unroll
        for (int nt = 0; nt < 8; ++nt) {
            mma8(X[nt], aA[kt], vb[nt * 8], vb[nt * 8 + 4 * VPW]);
        }
    }

    // ---- Epilogue: direct STG.64, rows 16w+g and 16w+8+g ----
    float* ob = O + site * 2048 + (16 * w + g) * 64 + 2 * t;
    #pragma unroll
    for (int nt = 0; nt < 8; ++nt) {
        *(float2*)(ob + nt * 8)            = make_float2(X[nt][0], X[nt][1]);
        *(float2*)(ob + 8 * 64 + nt * 8)   = make_float2(X[nt][2], X[nt][3]);
    }
}

extern "C" void kernel_launch(void* const* d_in, const int* in_sizes, int n_in,
                              void* d_out, int out_size) {
    const float* Q = (const float*)d_in[0];
    const float* K = (const float*)d_in[1];
    const float* V = (const float*)d_in[2];
    float* O = (float*)d_out;
    int nsites = in_sizes[0] / 2048;   // B*L = 16384
    linattn_kernel<<<nsites, 64>>>(Q, K, V, O);
}